// round 13
// baseline (speedup 1.0000x reference)
#include <cuda_runtime.h>

#define PH 7
#define PW 7
#define ROI_SCALE 0.0625f

#define N_IMG 4
#define C_DIM 128
#define H_DIM 50
#define W_DIM 50
#define HW (H_DIM * W_DIM)

// Bit-exact vs the as-executed JAX reference: x/7 computed as x * fl(1/7),
// fl(1/7) = 0x3E124925 (rounds up). DO NOT change.
#define RECIP7_BITS 0x3E124925u

// NHWC scratch: [b][h][w][c]  (5.12 MB static device array)
__device__ float g_featT[N_IMG * HW * C_DIM];

// ---------------- NCHW -> NHWC transpose ------------------------------------
__global__ void transpose_kernel(const float* __restrict__ feat) {
    __shared__ float tile[32][33];
    int b   = blockIdx.z;
    int hw0 = blockIdx.x * 32;
    int c0  = blockIdx.y * 32;

    const float* src = feat + (size_t)b * C_DIM * HW;
    float* dst = g_featT + (size_t)b * HW * C_DIM;

    int tx = threadIdx.x;   // 0..31
    int ty = threadIdx.y;   // 0..7

#pragma unroll
    for (int j = 0; j < 32; j += 8) {
        int c  = c0 + ty + j;
        int hw = hw0 + tx;
        if (hw < HW)
            tile[ty + j][tx] = src[c * HW + hw];
    }
    __syncthreads();
#pragma unroll
    for (int j = 0; j < 32; j += 8) {
        int hw = hw0 + ty + j;
        int c  = c0 + tx;
        if (hw < HW)
            dst[hw * C_DIM + c] = tile[tx][ty + j];
    }
}

// ------- pooling: block = (k, ph); warp handles pw = {wid, wid+4};
//         lane carries 4 channels via float4; smem-staged coalesced output ---
__global__ void __launch_bounds__(C_DIM) roi_pool_kernel(
        const float* __restrict__ rois,
        float* __restrict__ out) {
    __shared__ float tile[PW][C_DIM];

    int k    = blockIdx.x;
    int ph   = blockIdx.y;
    int wid  = threadIdx.x >> 5;
    int lane = threadIdx.x & 31;

    // Uniform per-block decode.
    const float* r = rois + k * 5;
    int b  = (int)r[0];
    int x1 = (int)rintf(__fmul_rn(r[1], ROI_SCALE));
    int y1 = (int)rintf(__fmul_rn(r[2], ROI_SCALE));
    int x2 = (int)rintf(__fmul_rn(r[3], ROI_SCALE));
    int y2 = (int)rintf(__fmul_rn(r[4], ROI_SCALE));

    float roi_w = (float)max(x2 - x1 + 1, 1);
    float roi_h = (float)max(y2 - y1 + 1, 1);
    const float recip7 = __uint_as_float(RECIP7_BITS);
    float bin_w = __fmul_rn(roi_w, recip7);
    float bin_h = __fmul_rn(roi_h, recip7);

    float phf = (float)ph;
    int hstart = min(max((int)floorf(__fmul_rn(phf, bin_h)) + y1, 0), H_DIM);
    int hend   = min(max((int)ceilf(__fmul_rn(phf + 1.0f, bin_h)) + y1, 0), H_DIM);
    bool hempty = (hend <= hstart);

    const float* baseb = g_featT + (size_t)b * HW * C_DIM;

#pragma unroll
    for (int i = 0; i < 2; ++i) {
        int pw = wid + 4 * i;
        if (pw >= PW) break;

        float pwf = (float)pw;
        int wstart = min(max((int)floorf(__fmul_rn(pwf, bin_w)) + x1, 0), W_DIM);
        int wend   = min(max((int)ceilf(__fmul_rn(pwf + 1.0f, bin_w)) + x1, 0), W_DIM);
        bool empty = hempty || (wend <= wstart);

        float4 m = make_float4(-1e30f, -1e30f, -1e30f, -1e30f);
        for (int h = hstart; h < hend; ++h) {
            const float* rowp = baseb + (h * W_DIM) * C_DIM + lane * 4;
            for (int w = wstart; w < wend; ++w) {
                float4 v = *(const float4*)(rowp + w * C_DIM);  // LDG.128
                m.x = fmaxf(m.x, v.x);
                m.y = fmaxf(m.y, v.y);
                m.z = fmaxf(m.z, v.z);
                m.w = fmaxf(m.w, v.w);
            }
        }
        if (empty) m = make_float4(0.0f, 0.0f, 0.0f, 0.0f);
        *(float4*)&tile[pw][lane * 4] = m;
    }
    __syncthreads();

    // Coalesced-ish writeback: thread t = channel t, writes its 7 contiguous
    // outputs (28B) at out[(k*C + t)*49 + ph*7].
    int t = threadIdx.x;
    float* op = out + ((size_t)k * C_DIM + t) * (PH * PW) + ph * PW;
#pragma unroll
    for (int j = 0; j < PW; ++j)
        op[j] = tile[j][t];
}

extern "C" void kernel_launch(void* const* d_in, const int* in_sizes, int n_in,
                              void* d_out, int out_size) {
    const float* feat = (const float*)d_in[0];
    const float* rois = (const float*)d_in[1];
    float* out = (float*)d_out;

    int K = in_sizes[1] / 5;   // 256

    dim3 tgrid((HW + 31) / 32, C_DIM / 32, N_IMG);
    dim3 tblk(32, 8);
    transpose_kernel<<<tgrid, tblk>>>(feat);

    dim3 pgrid(K, PH);          // 256 x 7 = 1792 blocks, 128 threads
    roi_pool_kernel<<<pgrid, C_DIM>>>(rois, out);
}

// round 15
// speedup vs baseline: 1.1951x; 1.1951x over previous
#include <cuda_runtime.h>

#define PH 7
#define PW 7
#define ROI_SCALE 0.0625f

#define N_IMG 4
#define C_DIM 128
#define H_DIM 50
#define W_DIM 50
#define HW (H_DIM * W_DIM)
#define BINS 49
#define K_ROIS 256

// Bit-exact vs the as-executed JAX reference: x/7 computed as x * fl(1/7),
// fl(1/7) = 0x3E124925 (rounds up). DO NOT change.
#define RECIP7_BITS 0x3E124925u

// NHWC scratch: [b][h][w][c]  (5.12 MB static device array)
__device__ float g_featT[N_IMG * HW * C_DIM];
// NHWC-ordered pooled scratch: [k][ph*7+pw][c]  (6.4 MB)
__device__ float g_out2[K_ROIS * BINS * C_DIM];

// ---------------- NCHW -> NHWC transpose ------------------------------------
__global__ void transpose_kernel(const float* __restrict__ feat) {
    __shared__ float tile[32][33];
    int b   = blockIdx.z;
    int hw0 = blockIdx.x * 32;
    int c0  = blockIdx.y * 32;

    const float* src = feat + (size_t)b * C_DIM * HW;
    float* dst = g_featT + (size_t)b * HW * C_DIM;

    int tx = threadIdx.x;   // 0..31
    int ty = threadIdx.y;   // 0..7

#pragma unroll
    for (int j = 0; j < 32; j += 8) {
        int c  = c0 + ty + j;
        int hw = hw0 + tx;
        if (hw < HW)
            tile[ty + j][tx] = src[c * HW + hw];
    }
    __syncthreads();
#pragma unroll
    for (int j = 0; j < 32; j += 8) {
        int hw = hw0 + ty + j;
        int c  = c0 + tx;
        if (hw < HW)
            dst[hw * C_DIM + c] = tile[tx][ty + j];
    }
}

// -------- pooling: warp = one (k, ph, pw) bin; lane = 4 channels (float4) ---
__global__ void __launch_bounds__(64) roi_pool_kernel(
        const float* __restrict__ rois) {
    int wg   = (blockIdx.x << 1) + (threadIdx.x >> 5);   // global warp id
    int lane = threadIdx.x & 31;

    int k   = wg / BINS;
    int rem = wg - k * BINS;
    int ph  = rem / PW;
    int pw  = rem - ph * PW;

    // Warp-uniform decode.
    const float* r = rois + k * 5;
    int b  = (int)r[0];
    int x1 = (int)rintf(__fmul_rn(r[1], ROI_SCALE));
    int y1 = (int)rintf(__fmul_rn(r[2], ROI_SCALE));
    int x2 = (int)rintf(__fmul_rn(r[3], ROI_SCALE));
    int y2 = (int)rintf(__fmul_rn(r[4], ROI_SCALE));

    float roi_w = (float)max(x2 - x1 + 1, 1);
    float roi_h = (float)max(y2 - y1 + 1, 1);
    const float recip7 = __uint_as_float(RECIP7_BITS);
    float bin_w = __fmul_rn(roi_w, recip7);
    float bin_h = __fmul_rn(roi_h, recip7);

    float phf = (float)ph;
    float pwf = (float)pw;
    int hstart = min(max((int)floorf(__fmul_rn(phf, bin_h)) + y1, 0), H_DIM);
    int hend   = min(max((int)ceilf(__fmul_rn(phf + 1.0f, bin_h)) + y1, 0), H_DIM);
    int wstart = min(max((int)floorf(__fmul_rn(pwf, bin_w)) + x1, 0), W_DIM);
    int wend   = min(max((int)ceilf(__fmul_rn(pwf + 1.0f, bin_w)) + x1, 0), W_DIM);

    const float* baseb = g_featT + (size_t)b * HW * C_DIM + lane * 4;

    float4 m0 = make_float4(-1e30f, -1e30f, -1e30f, -1e30f);
    float4 m1 = m0;
    for (int h = hstart; h < hend; ++h) {
        const float* rowp = baseb + (h * W_DIM) * C_DIM;
        int w = wstart;
        for (; w + 1 < wend; w += 2) {
            float4 v0 = *(const float4*)(rowp + w * C_DIM);
            float4 v1 = *(const float4*)(rowp + (w + 1) * C_DIM);
            m0.x = fmaxf(m0.x, v0.x); m0.y = fmaxf(m0.y, v0.y);
            m0.z = fmaxf(m0.z, v0.z); m0.w = fmaxf(m0.w, v0.w);
            m1.x = fmaxf(m1.x, v1.x); m1.y = fmaxf(m1.y, v1.y);
            m1.z = fmaxf(m1.z, v1.z); m1.w = fmaxf(m1.w, v1.w);
        }
        if (w < wend) {
            float4 v0 = *(const float4*)(rowp + w * C_DIM);
            m0.x = fmaxf(m0.x, v0.x); m0.y = fmaxf(m0.y, v0.y);
            m0.z = fmaxf(m0.z, v0.z); m0.w = fmaxf(m0.w, v0.w);
        }
    }
    float4 m;
    m.x = fmaxf(m0.x, m1.x); m.y = fmaxf(m0.y, m1.y);
    m.z = fmaxf(m0.z, m1.z); m.w = fmaxf(m0.w, m1.w);

    if ((hend <= hstart) || (wend <= wstart))
        m = make_float4(0.0f, 0.0f, 0.0f, 0.0f);

    // Coalesced 512B store per warp.
    *(float4*)(g_out2 + (size_t)wg * C_DIM + lane * 4) = m;
}

// ------- per-ROI transpose [49][128] -> [128][49] into final output ---------
__global__ void __launch_bounds__(256) untranspose_kernel(float* __restrict__ out) {
    __shared__ float s[BINS * 129];   // stride 129 -> conflict-free
    int k   = blockIdx.x;
    int tid = threadIdx.x;

    const float* src = g_out2 + (size_t)k * BINS * C_DIM;   // [j][c]
    for (int i = tid; i < BINS * C_DIM; i += 256) {
        int j = i >> 7;          // /128
        int c = i & 127;
        s[j * 129 + c] = src[i];
    }
    __syncthreads();

    float* dst = out + (size_t)k * C_DIM * BINS;            // [c][j]
    for (int i = tid; i < C_DIM * BINS; i += 256) {
        int c = i / BINS;
        int j = i - c * BINS;
        dst[i] = s[j * 129 + c];
    }
}

extern "C" void kernel_launch(void* const* d_in, const int* in_sizes, int n_in,
                              void* d_out, int out_size) {
    const float* feat = (const float*)d_in[0];
    const float* rois = (const float*)d_in[1];
    float* out = (float*)d_out;

    dim3 tgrid((HW + 31) / 32, C_DIM / 32, N_IMG);
    dim3 tblk(32, 8);
    transpose_kernel<<<tgrid, tblk>>>(feat);

    int nwarps = K_ROIS * BINS;                 // 12544
    roi_pool_kernel<<<nwarps / 2, 64>>>(rois);  // 6272 blocks x 2 warps

    untranspose_kernel<<<K_ROIS, 256>>>(out);
}